// round 9
// baseline (speedup 1.0000x reference)
#include <cuda_runtime.h>
#include <cstdint>

#define FG_IOU 0.7f
#define BG_IOU 0.3f
#define IMG    640.0f

// Scratch for per-(b,g) best-anchor packed keys: (iou_bits << 32) | ~anchor_idx.
// Zero-initialized at module load; the last block resets it each call, so every
// kernel_launch starts from a clean state (graph-replay deterministic).
__device__ unsigned long long g_best[8192];
__device__ unsigned int g_ctr = 0;

// Fused kernel: main assignment pass + last-block rule-1 apply.
// Main pass: 4 anchors/thread (block covers 1024 anchors); 64 gts in smem.
// Rules 2 & 3 + max_iou computed directly. Rule-1 candidates (per-gt argmax
// over anchors) tracked via block-local running max in smem, seeded from the
// global running max, with a REDUX.MAX-gated atomic path.
__global__ __launch_bounds__(256) void assign_fused_kernel(
    const float4* __restrict__ anchors,   // [B,A] cxcywh
    const float4* __restrict__ gts,       // [B,G] xyxy
    float*  __restrict__ out_labels,      // [B,A]
    float4* __restrict__ out_matched,     // [B,A]
    float*  __restrict__ out_maxiou,      // [B,A]
    int A, int G, int B, int nblocks)
{
    __shared__ float4 sgt[64];
    __shared__ float  sarea[64];
    __shared__ unsigned long long spm[64];   // packed (iou_bits<<32)|~a, block running max

    const int b = blockIdx.y;
    const int t = threadIdx.x;

    if (t < G) {
        float4 g = gts[b * G + t];
        sgt[t]   = g;
        sarea[t] = (g.z - g.x) * (g.w - g.y);
        // Seed from global running max (other blocks' progress). Racy/stale reads
        // are only smaller -> conservative-safe; final result unaffected.
        unsigned long long seed;
        asm volatile("ld.global.cg.u64 %0, [%1];" : "=l"(seed) : "l"(&g_best[b * G + t]));
        spm[t] = seed;
    }
    __syncthreads();

    const int base = blockIdx.x * 1024;
    const long long abase = (long long)b * A;

    float ax1[4], ay1[4], ax2[4], ay2[4], area[4], best[4];
    int   bestg[4], aidx[4];
    unsigned inv[4];

#pragma unroll
    for (int k = 0; k < 4; k++) {
        int a = base + k * 256 + t;
        aidx[k] = a;
        if (a >= A) a = A - 1;                // A % 1024 == 0 in practice; safety only
        float4 an = __ldg(&anchors[abase + a]);
        ax1[k] = an.x - 0.5f * an.z;
        ay1[k] = an.y - 0.5f * an.w;
        ax2[k] = an.x + 0.5f * an.z;
        ay2[k] = an.y + 0.5f * an.w;
        area[k] = (ax2[k] - ax1[k]) * (ay2[k] - ay1[k]);
        best[k] = -1.0f;
        bestg[k] = 0;
        inv[k] = ~(unsigned)a;                // larger inv == smaller index -> first-occurrence tiebreak
    }

#pragma unroll 8
    for (int g = 0; g < G; g++) {
        const float4 gb = sgt[g];
        const float  ga = sarea[g];
        // Racy snapshot of current block-best iou bits (non-negative float bits
        // order as u32). Stale => smaller => conservative-safe.
        const unsigned thr = ((const volatile unsigned*)&spm[g])[1];

        float iou[4];
#pragma unroll
        for (int k = 0; k < 4; k++) {
            float ltx = fmaxf(ax1[k], gb.x);
            float lty = fmaxf(ay1[k], gb.y);
            float rbx = fminf(ax2[k], gb.z);
            float rby = fminf(ay2[k], gb.w);
            float w = fmaxf(rbx - ltx, 0.0f);
            float h = fmaxf(rby - lty, 0.0f);
            float inter = w * h;
            float uni = (area[k] + ga) - inter;      // > 0 always (boxes have area)
            iou[k] = __fdividef(inter, uni);
            if (iou[k] > best[k]) { best[k] = iou[k]; bestg[k] = g; }  // strict > => first max
        }
        // Tree max (better ILP than serial chain).
        float mx = fmaxf(fmaxf(iou[0], iou[1]), fmaxf(iou[2], iou[3]));
        // Single HW warp reduction; branch is warp-uniform.
        unsigned wmax = __reduce_max_sync(0xFFFFFFFFu, __float_as_uint(mx));
        if (wmax > thr) {
#pragma unroll
            for (int k = 0; k < 4; k++) {
                if (__float_as_uint(iou[k]) == wmax)
                    atomicMax(&spm[g],
                              ((unsigned long long)wmax << 32) | (unsigned long long)inv[k]);
            }
        }
    }

    // Per-anchor epilogue: rules 2 & 3 + cross filter.
#pragma unroll
    for (int k = 0; k < 4; k++) {
        if (aidx[k] >= A) continue;
        float mv = best[k];
        bool fg = mv > FG_IOU;
        float lab = fg ? 1.0f : ((mv < BG_IOU) ? 0.0f : -1.0f);
        bool cross = (ax1[k] < 0.0f) | (ay1[k] < 0.0f) | (ax2[k] > IMG) | (ay2[k] > IMG);
        if (cross) lab = -1.0f;                    // cross filter affects labels only
        float4 m = make_float4(0.f, 0.f, 0.f, 0.f);
        if (fg) m = sgt[bestg[k]];                 // rule-2 matched box
        long long o = abase + aidx[k];
        out_labels[o]  = lab;
        out_matched[o] = m;
        out_maxiou[o]  = mv;
    }

    // Flush block-best keys to global, filtered through an L2 read (stale reads
    // are only smaller -> possibly redundant atomic, never a skipped one).
    __syncthreads();
    if (t < G) {
        unsigned long long v = spm[t];
        unsigned long long* p = &g_best[b * G + t];
        unsigned long long cur;
        asm volatile("ld.global.cg.u64 %0, [%1];" : "=l"(cur) : "l"(p));
        if (v > cur) atomicMax(p, v);
    }

    // Release: every thread fences so each flusher's atomic is globally visible
    // before the barrier; then t0 takes a ticket.
    __threadfence();
    __syncthreads();
    __shared__ int s_last;
    if (t == 0) {
        unsigned old = atomicAdd(&g_ctr, 1u);
        s_last = (old == (unsigned)(nblocks - 1)) ? 1 : 0;
    }
    __syncthreads();
    if (!s_last) return;

    // ---- Last block only: rule-1 apply for all batches. ----
    // Reference order: rule1 sets label/matched, THEN rule2 overrides matched
    // where fg, THEN cross filter zaps labels. Equivalent post-pass:
    //   label[best_a]   = cross ? -1 : 1   (always)
    //   matched[best_a] = gt[g]            (only where NOT fg)
    // Duplicate best-anchors resolved last-g-wins within a batch (labels are
    // identical for duplicates: they depend only on the anchor).
    __threadfence();                         // acquire
    __shared__ int s_a[512];                 // B*G <= 512 here

    const int NE = B * G;
    int   e_a[2];
    float e_lab[2];
    int   e_fg[2];
    float4 e_gt[2];

    for (int r = 0; r < 2; r++) {
        int e = t + r * 256;
        e_a[r] = -1;
        if (e < NE) {
            int bb = e / G;
            unsigned long long v;
            asm volatile("ld.global.cg.u64 %0, [%1];" : "=l"(v) : "l"(&g_best[e]));
            g_best[e] = 0ULL;                // reset scratch for next launch
            unsigned a = ~(unsigned)(v & 0xFFFFFFFFull);
            if (a < (unsigned)A) {
                e_a[r] = (int)a;
                long long o = (long long)bb * A + a;
                float mv = out_maxiou[o];
                float4 an = anchors[o];
                float x1 = an.x - 0.5f * an.z, y1 = an.y - 0.5f * an.w;
                float x2 = an.x + 0.5f * an.z, y2 = an.y + 0.5f * an.w;
                bool cross = (x1 < 0.0f) || (y1 < 0.0f) || (x2 > IMG) || (y2 > IMG);
                e_lab[r] = cross ? -1.0f : 1.0f;
                e_fg[r]  = (mv > FG_IOU) ? 1 : 0;
                e_gt[r]  = gts[e];
            }
        }
        if (e < 512) s_a[e] = e_a[r];
    }
    __syncthreads();

    for (int r = 0; r < 2; r++) {
        int e = t + r * 256;
        if (e >= NE || e_a[r] < 0) continue;
        int bb = e / G;
        int gg = e - bb * G;
        // Later g with the same anchor in the same batch wins (matches the
        // serialized scatter order of the reference).
        bool later_dup = false;
        for (int j = gg + 1; j < G; j++) later_dup |= (s_a[bb * G + j] == e_a[r]);
        if (!later_dup) {
            long long o = (long long)bb * A + e_a[r];
            out_labels[o] = e_lab[r];
            if (!e_fg[r]) out_matched[o] = e_gt[r];
        }
    }

    if (t == 0) g_ctr = 0;                   // reset for next launch (we are alone now)
}

extern "C" void kernel_launch(void* const* d_in, const int* in_sizes, int n_in,
                              void* d_out, int out_size)
{
    const float4* anchors = (const float4*)d_in[0];   // [B,A,4] cxcywh
    const float4* gts     = (const float4*)d_in[1];   // [B,G,4] xyxy

    const int G = 64;
    int nA = in_sizes[0];
    int nG = in_sizes[1];
    int B  = nG / (G * 4);
    int A  = nA / (B * 4);

    float*  out         = (float*)d_out;
    float*  out_labels  = out;                                  // [B*A]
    float4* out_matched = (float4*)(out + (long long)B * A);    // [B*A] float4
    float*  out_maxiou  = out + (long long)B * A * 5;           // [B*A]

    dim3 grid((A + 1023) / 1024, B);
    int nblocks = grid.x * grid.y;
    assign_fused_kernel<<<grid, 256>>>(anchors, gts, out_labels, out_matched,
                                       out_maxiou, A, G, B, nblocks);
}